// round 3
// baseline (speedup 1.0000x reference)
#include <cuda_runtime.h>
#include <cuda_bf16.h>
#include <cstdint>

// Problem constants
#define BB 32
#define NN 1024
#define IN_DIM 64
#define HID 128
#define OUTD 64        // 2*LAT
#define NUM_LAYERS 3

// Scratch (device globals; no allocations allowed)
__device__ float g_h[BB * NN * HID];     // 16 MB
__device__ float g_msg[BB * NN * HID];   // 16 MB

// ----------------------------------------------------------------------------
// Row-wise small GEMM: C[rows, OUT] = act( A[rows, K] @ W[K, OUT] (+bias) ) (*mask)
// 256 threads, 32 rows/block. K-chunked smem staging of W and A.
// Thread t owns row r = t>>3 and columns {cg + 8*j}, cg = t&7 (conflict-free sW reads,
// full-sector stores).
// ----------------------------------------------------------------------------
template<int K, int OUT, bool HAS_BIAS, bool HAS_MASK>
__global__ __launch_bounds__(256) void rowgemm_kernel(
    const float* __restrict__ A, const float* __restrict__ W,
    const float* __restrict__ bias, const float* __restrict__ mask,
    float* __restrict__ C)
{
    constexpr int ROWS = 32;
    constexpr int CPT = OUT / 8;   // columns per thread
    __shared__ float sW[32][OUT];
    __shared__ float sA[ROWS][33]; // +1 pad: conflict-free row broadcast

    const int tid = threadIdx.x;
    const int r   = tid >> 3;
    const int cg  = tid & 7;
    const int row0 = blockIdx.x * ROWS;

    float acc[CPT];
#pragma unroll
    for (int j = 0; j < CPT; j++) acc[j] = 0.f;

    for (int kc = 0; kc < K; kc += 32) {
        // stage W chunk [32, OUT]
        for (int idx = tid; idx < 32 * OUT; idx += 256) {
            int kk = idx / OUT, cc = idx % OUT;
            sW[kk][cc] = W[(kc + kk) * OUT + cc];
        }
        // stage A chunk [ROWS, 32]
        for (int idx = tid; idx < ROWS * 32; idx += 256) {
            int rr = idx >> 5, kk = idx & 31;
            sA[rr][kk] = A[(size_t)(row0 + rr) * K + kc + kk];
        }
        __syncthreads();
#pragma unroll
        for (int k = 0; k < 32; k++) {
            float a = sA[r][k];
#pragma unroll
            for (int j = 0; j < CPT; j++)
                acc[j] += a * sW[k][cg + 8 * j];
        }
        __syncthreads();
    }

    const int row = row0 + r;
    float m = 1.f;
    if (HAS_MASK) m = mask[row];
#pragma unroll
    for (int j = 0; j < CPT; j++) {
        float v = acc[j];
        if (HAS_BIAS) v += bias[cg + 8 * j];
        if (HAS_MASK) v *= m;
        C[(size_t)row * OUT + cg + 8 * j] = v;
    }
}

// ----------------------------------------------------------------------------
// Big batched GEMM + ReLU:  h[b] = relu( adj[b] (1024x1024) @ msg[b] (1024x128) )
// BM=128, BN=128, BK=16, 256 threads, 8x8 microtile. grid = (8 row tiles, 32 batches).
// 256 blocks @ 2 blocks/SM -> single wave on 148 SMs.
// ----------------------------------------------------------------------------
__global__ __launch_bounds__(256, 2) void adj_gemm_relu_kernel(
    const float* __restrict__ adj, const float* __restrict__ Bm,
    float* __restrict__ C)
{
    constexpr int BM = 128, BN = 128, BK = 16;
    __shared__ float As[BK][BM + 4];   // stride 132: breaks transpose-store conflicts
    __shared__ float Bs[BK][BN];

    const int b = blockIdx.y;
    const float* A  = adj + (size_t)b * NN * NN;
    const float* B  = Bm  + (size_t)b * NN * HID;
    float*       Cc = C   + (size_t)b * NN * HID;

    const int tid = threadIdx.x;
    const int tx = tid & 15;        // 0..15 -> cols tx*8..
    const int ty = tid >> 4;        // 0..15 -> rows ty*8..
    const int row0 = blockIdx.x * BM;

    float acc[8][8];
#pragma unroll
    for (int i = 0; i < 8; i++)
#pragma unroll
        for (int j = 0; j < 8; j++) acc[i][j] = 0.f;

    for (int k0 = 0; k0 < NN; k0 += BK) {
        // load A tile: 128 rows x 16 k  (512 float4, 2 per thread), store transposed
#pragma unroll
        for (int i = 0; i < 2; i++) {
            int f  = tid + i * 256;
            int m  = f >> 2;
            int kq = f & 3;
            float4 v = *reinterpret_cast<const float4*>(
                &A[(size_t)(row0 + m) * NN + k0 + kq * 4]);
            As[kq * 4 + 0][m] = v.x;
            As[kq * 4 + 1][m] = v.y;
            As[kq * 4 + 2][m] = v.z;
            As[kq * 4 + 3][m] = v.w;
        }
        // load B tile: 16 k x 128 n (512 float4, 2 per thread)
#pragma unroll
        for (int i = 0; i < 2; i++) {
            int f  = tid + i * 256;
            int kk = f >> 5;
            int nq = f & 31;
            *reinterpret_cast<float4*>(&Bs[kk][nq * 4]) =
                *reinterpret_cast<const float4*>(&B[(size_t)(k0 + kk) * HID + nq * 4]);
        }
        __syncthreads();

#pragma unroll
        for (int k = 0; k < BK; k++) {
            float ra[8], rb[8];
#pragma unroll
            for (int i = 0; i < 8; i++) ra[i] = As[k][ty * 8 + i];
#pragma unroll
            for (int j = 0; j < 8; j++) rb[j] = Bs[k][tx * 8 + j];
#pragma unroll
            for (int i = 0; i < 8; i++)
#pragma unroll
                for (int j = 0; j < 8; j++)
                    acc[i][j] += ra[i] * rb[j];
        }
        __syncthreads();
    }

    // epilogue: ReLU + vectorized store
#pragma unroll
    for (int i = 0; i < 8; i++) {
        int m = row0 + ty * 8 + i;
#pragma unroll
        for (int j = 0; j < 8; j += 4) {
            float4 v;
            v.x = fmaxf(acc[i][j + 0], 0.f);
            v.y = fmaxf(acc[i][j + 1], 0.f);
            v.z = fmaxf(acc[i][j + 2], 0.f);
            v.w = fmaxf(acc[i][j + 3], 0.f);
            *reinterpret_cast<float4*>(&Cc[(size_t)m * HID + tx * 8 + j]) = v;
        }
    }
}

// ----------------------------------------------------------------------------
// Launch
// Inputs (metadata order):
//   0: node_features   [B, N, 64]   f32
//   1: adjacency_matrix[B, N, N]    f32
//   2: node_mask       [B, N, 1]    f32
//   3: W_embed         [64, 128]    f32
//   4: Wl              [3, 128, 128]f32
//   5: bl              [3, 128]     f32
//   6: W_proj          [128, 64]    f32
//   7: b_proj          [64]         f32
// Output: [B, N, 64] f32
// ----------------------------------------------------------------------------
extern "C" void kernel_launch(void* const* d_in, const int* in_sizes, int n_in,
                              void* d_out, int out_size)
{
    const float* x      = (const float*)d_in[0];
    const float* adj    = (const float*)d_in[1];
    const float* mask   = (const float*)d_in[2];
    const float* Wemb   = (const float*)d_in[3];
    const float* Wl     = (const float*)d_in[4];
    const float* bl     = (const float*)d_in[5];
    const float* Wproj  = (const float*)d_in[6];
    const float* bproj  = (const float*)d_in[7];
    float* out = (float*)d_out;

    float *h_ptr = nullptr, *msg_ptr = nullptr;
    cudaGetSymbolAddress((void**)&h_ptr, g_h);
    cudaGetSymbolAddress((void**)&msg_ptr, g_msg);

    const int nrows = BB * NN;                 // 32768
    dim3 rowgrid(nrows / 32);                  // 1024 blocks

    // 1) embed: h = x @ W_embed   (no bias)
    rowgemm_kernel<IN_DIM, HID, false, false><<<rowgrid, 256>>>(
        x, Wemb, nullptr, nullptr, h_ptr);

    // 2) GCN layers
    dim3 bigg(NN / 128, BB);                   // (8, 32) = 256 blocks
    for (int l = 0; l < NUM_LAYERS; l++) {
        rowgemm_kernel<HID, HID, true, false><<<rowgrid, 256>>>(
            h_ptr, Wl + (size_t)l * HID * HID, bl + (size_t)l * HID, nullptr, msg_ptr);
        adj_gemm_relu_kernel<<<bigg, 256>>>(adj, msg_ptr, h_ptr);
    }

    // 3) projection + mask: out = (h @ W_proj + b_proj) * mask
    rowgemm_kernel<HID, OUTD, true, true><<<rowgrid, 256>>>(
        h_ptr, Wproj, bproj, mask, out);
}

// round 5
// speedup vs baseline: 2.8905x; 2.8905x over previous
#include <cuda_runtime.h>
#include <cuda_bf16.h>
#include <cstdint>

// Problem constants
#define BB 32
#define NN 1024
#define IN_DIM 64
#define HID 128
#define OUTD 64        // 2*LAT
#define NUM_LAYERS 3

// Scratch (device globals; no allocations allowed)
__device__ float g_h[BB * NN * HID];        // 16 MB, h activations [b*N + node][HID]
__device__ float g_msgT[BB * HID * NN];     // 16 MB, msg transposed: [b][n(128)][node(1024)]

// ============================================================================
// Helpers (plain sm_100-compatible: mma.sync tf32 + cp.async)
// ============================================================================
__device__ __forceinline__ uint32_t f2tf32(float f) {
    uint32_t r;
    asm("cvt.rna.tf32.f32 %0, %1;" : "=r"(r) : "f"(f));
    return r;
}

__device__ __forceinline__ void mma_tf32(float c[4],
                                         uint32_t a0, uint32_t a1, uint32_t a2, uint32_t a3,
                                         uint32_t b0, uint32_t b1) {
    asm volatile(
        "mma.sync.aligned.m16n8k8.row.col.f32.tf32.tf32.f32 "
        "{%0,%1,%2,%3}, {%4,%5,%6,%7}, {%8,%9}, {%0,%1,%2,%3};"
        : "+f"(c[0]), "+f"(c[1]), "+f"(c[2]), "+f"(c[3])
        : "r"(a0), "r"(a1), "r"(a2), "r"(a3), "r"(b0), "r"(b1));
}

#define CP_ASYNC16(dst, src) \
    asm volatile("cp.async.cg.shared.global [%0], [%1], 16;" :: "r"(dst), "l"(src))
#define CP_COMMIT() asm volatile("cp.async.commit_group;" ::: "memory")
#define CP_WAIT2()  asm volatile("cp.async.wait_group 2;" ::: "memory")

__device__ __forceinline__ uint32_t smem_u32(const void* p) {
    uint32_t a;
    asm("{ .reg .u64 t; cvta.to.shared.u64 t, %1; cvt.u32.u64 %0, t; }"
        : "=r"(a) : "l"(p));
    return a;
}

// Tile layout: 128 rows x 32 floats (128B). 16B words XOR-swizzled by (row&7):
// phys = row*128 + ((q ^ (row&7))<<4) + inner, q = 16B word index 0..7.
// Fragment LDS from this layout is bank-conflict-free (see analysis).
__device__ __forceinline__ float lds_sw(const char* tile, int row, int col) {
    int q   = col >> 2;
    int off = row * 128 + (((q ^ (row & 7)) << 4)) + ((col & 3) << 2);
    return *reinterpret_cast<const float*>(tile + off);
}

// ============================================================================
// Register-tiled side GEMM: C = (A[M,K] @ W[K,BN] + bias) (* mask), optional
// transposed output (for msgT). 256 threads, BM=128, BK=16, 8 x VN microtile.
// ============================================================================
template<int K, int BN, bool BIAS, bool MASK, bool TRANS>
__global__ __launch_bounds__(256) void tile_gemm(
    const float* __restrict__ A, const float* __restrict__ W,
    const float* __restrict__ bias, const float* __restrict__ mask,
    float* __restrict__ C)
{
    constexpr int BM = 128, BK = 16;
    constexpr int VN = BN / 16;           // cols per thread (8 or 4)
    __shared__ float As[BK][BM + 4];
    __shared__ float Bs[BK][BN];

    const int tid  = threadIdx.x;
    const int tx   = tid & 15;
    const int ty   = tid >> 4;
    const int row0 = blockIdx.x * BM;
    const int col0 = tx * VN;

    float acc[8][VN];
#pragma unroll
    for (int i = 0; i < 8; i++)
#pragma unroll
        for (int j = 0; j < VN; j++) acc[i][j] = 0.f;

    for (int k0 = 0; k0 < K; k0 += BK) {
        // A tile: 128 rows x 16 k = 512 float4, stored transposed
#pragma unroll
        for (int i = 0; i < 2; i++) {
            int f = tid + i * 256;
            int m = f >> 2, kq = f & 3;
            float4 v = *reinterpret_cast<const float4*>(
                &A[(size_t)(row0 + m) * K + k0 + kq * 4]);
            As[kq * 4 + 0][m] = v.x;
            As[kq * 4 + 1][m] = v.y;
            As[kq * 4 + 2][m] = v.z;
            As[kq * 4 + 3][m] = v.w;
        }
        // B tile: 16 k x BN
#pragma unroll
        for (int i = 0; i < (BK * BN) / (4 * 256); i++) {
            int f  = tid + i * 256;
            int kk = f / (BN / 4);
            int nq = f % (BN / 4);
            *reinterpret_cast<float4*>(&Bs[kk][nq * 4]) =
                *reinterpret_cast<const float4*>(&W[(size_t)(k0 + kk) * BN + nq * 4]);
        }
        __syncthreads();

#pragma unroll
        for (int k = 0; k < BK; k++) {
            float ra[8], rb[VN];
#pragma unroll
            for (int i = 0; i < 8; i++)  ra[i] = As[k][ty * 8 + i];
#pragma unroll
            for (int j = 0; j < VN; j++) rb[j] = Bs[k][col0 + j];
#pragma unroll
            for (int i = 0; i < 8; i++)
#pragma unroll
                for (int j = 0; j < VN; j++)
                    acc[i][j] += ra[i] * rb[j];
        }
        __syncthreads();
    }

    float bv[VN];
#pragma unroll
    for (int j = 0; j < VN; j++) bv[j] = BIAS ? bias[col0 + j] : 0.f;

    if (TRANS) {
        // C is msgT: [bb][n(HID)][node(NN)]
        const int bb    = row0 >> 10;
        const int node0 = (row0 & (NN - 1)) + ty * 8;
#pragma unroll
        for (int j = 0; j < VN; j++) {
            float* dst = &C[((size_t)(bb * HID + col0 + j)) * NN + node0];
#pragma unroll
            for (int i = 0; i < 8; i += 4) {
                float4 v;
                v.x = acc[i + 0][j] + bv[j];
                v.y = acc[i + 1][j] + bv[j];
                v.z = acc[i + 2][j] + bv[j];
                v.w = acc[i + 3][j] + bv[j];
                *reinterpret_cast<float4*>(&dst[i]) = v;
            }
        }
    } else {
#pragma unroll
        for (int i = 0; i < 8; i++) {
            int row = row0 + ty * 8 + i;
            float m = MASK ? mask[row] : 1.f;
#pragma unroll
            for (int j = 0; j < VN; j += 4) {
                float4 v;
                v.x = (acc[i][j + 0] + bv[j + 0]) * m;
                v.y = (acc[i][j + 1] + bv[j + 1]) * m;
                v.z = (acc[i][j + 2] + bv[j + 2]) * m;
                v.w = (acc[i][j + 3] + bv[j + 3]) * m;
                *reinterpret_cast<float4*>(&C[(size_t)row * BN + col0 + j]) = v;
            }
        }
    }
}

// ============================================================================
// Warp-MMA tf32 batched GEMM + ReLU:
//   h[b][m][n] = relu( sum_k adj[b][m][k] * msgT[b][n][k] )
// BM=128, BN=128 (=HID), K=1024 in BK=32 chunks. 8 warps in 2x4 grid; each warp
// computes 64x32 via 4x4 m16n8k8 tf32 mma.sync tiles. 3-stage cp.async ring,
// XOR-swizzled smem (no padding, conflict-free frag loads). 2 CTAs/SM.
// ============================================================================
#define ST 3
#define BKT 32
#define NIT (NN / BKT)              // 32
#define TILE_BYTES (128 * 128)      // 128 rows x 128B = 16 KB
#define SM_TOTAL (2 * ST * TILE_BYTES)  // 96 KB

__device__ __forceinline__ void load_tiles_mma(
    uint32_t aDst, uint32_t bDst,
    const float* __restrict__ Ab, const float* __restrict__ Bb,
    int k0, int tid)
{
#pragma unroll
    for (int i = 0; i < 4; i++) {
        int idx = tid + i * 256;                 // 0..1023
        int row = idx >> 3;                      // 0..127
        int q   = idx & 7;                       // 16B word
        uint32_t off = row * 128 + ((q ^ (row & 7)) << 4);
        CP_ASYNC16(aDst + off, Ab + (size_t)row * NN + k0 + q * 4);
    }
#pragma unroll
    for (int i = 0; i < 4; i++) {
        int idx = tid + i * 256;
        int row = idx >> 3;
        int q   = idx & 7;
        uint32_t off = row * 128 + ((q ^ (row & 7)) << 4);
        CP_ASYNC16(bDst + off, Bb + (size_t)row * NN + k0 + q * 4);
    }
}

__global__ __launch_bounds__(256, 2) void adj_mma_relu(
    const float* __restrict__ adj,
    const float* __restrict__ msgT,
    float* __restrict__ h)
{
    extern __shared__ char smem[];
    const uint32_t sb = smem_u32(smem);
    const int tid = threadIdx.x;
    const int wid = tid >> 5;
    const int lid = tid & 31;
    const int g   = lid >> 2;      // group id 0..7
    const int tg  = lid & 3;       // thread-in-group

    const int m_warp = (wid & 1) * 64;   // warp row offset within 128
    const int n_warp = (wid >> 1) * 32;  // warp col offset within 128

    const int b    = blockIdx.y;
    const int row0 = blockIdx.x * 128;

    const float* Ab = adj  + (size_t)b * NN * NN + (size_t)row0 * NN;
    const float* Bb = msgT + (size_t)b * HID * NN;

    float acc[4][4][4];
#pragma unroll
    for (int mt = 0; mt < 4; mt++)
#pragma unroll
        for (int nt = 0; nt < 4; nt++)
#pragma unroll
            for (int r = 0; r < 4; r++) acc[mt][nt][r] = 0.f;

    // Preload first ST chunks
#pragma unroll
    for (int p = 0; p < ST; p++) {
        load_tiles_mma(sb + p * TILE_BYTES, sb + (ST + p) * TILE_BYTES,
                       Ab, Bb, p * BKT, tid);
        CP_COMMIT();
    }

    for (int it = 0; it < NIT; it++) {
        const int s = it % ST;
        const char* As = smem + s * TILE_BYTES;
        const char* Bs = smem + (ST + s) * TILE_BYTES;

        CP_WAIT2();
        __syncthreads();

#pragma unroll
        for (int kk = 0; kk < 4; kk++) {        // 4 x K=8 steps within chunk
            const int c0 = kk * 8 + tg;
            // B fragments for the 4 n-tiles
            uint32_t bf[4][2];
#pragma unroll
            for (int nt = 0; nt < 4; nt++) {
                int nr = n_warp + nt * 8 + g;
                bf[nt][0] = f2tf32(lds_sw(Bs, nr, c0));
                bf[nt][1] = f2tf32(lds_sw(Bs, nr, c0 + 4));
            }
#pragma unroll
            for (int mt = 0; mt < 4; mt++) {
                int mr = m_warp + mt * 16 + g;
                uint32_t a0 = f2tf32(lds_sw(As, mr,     c0));
                uint32_t a1 = f2tf32(lds_sw(As, mr + 8, c0));
                uint32_t a2 = f2tf32(lds_sw(As, mr,     c0 + 4));
                uint32_t a3 = f2tf32(lds_sw(As, mr + 8, c0 + 4));
#pragma unroll
                for (int nt = 0; nt < 4; nt++)
                    mma_tf32(acc[mt][nt], a0, a1, a2, a3, bf[nt][0], bf[nt][1]);
            }
        }
        __syncthreads();

        if (it + ST < NIT)
            load_tiles_mma(sb + s * TILE_BYTES, sb + (ST + s) * TILE_BYTES,
                           Ab, Bb, (it + ST) * BKT, tid);
        CP_COMMIT();                              // empty group OK near tail
    }

    // Epilogue: ReLU + store. c0,c1 -> (row=g, col=2tg,2tg+1); c2,c3 -> row+8.
    float* Hc = h + (size_t)(b * NN + row0) * HID;
#pragma unroll
    for (int mt = 0; mt < 4; mt++) {
        int mr = m_warp + mt * 16 + g;
#pragma unroll
        for (int nt = 0; nt < 4; nt++) {
            int col = n_warp + nt * 8 + tg * 2;
            float2 v0, v1;
            v0.x = fmaxf(acc[mt][nt][0], 0.f);
            v0.y = fmaxf(acc[mt][nt][1], 0.f);
            v1.x = fmaxf(acc[mt][nt][2], 0.f);
            v1.y = fmaxf(acc[mt][nt][3], 0.f);
            *reinterpret_cast<float2*>(&Hc[(size_t)mr * HID + col])       = v0;
            *reinterpret_cast<float2*>(&Hc[(size_t)(mr + 8) * HID + col]) = v1;
        }
    }
}

// ============================================================================
// Launch
// Inputs: 0 node_features [B,N,64] | 1 adjacency [B,N,N] | 2 node_mask [B,N,1]
//         3 W_embed [64,128] | 4 Wl [3,128,128] | 5 bl [3,128]
//         6 W_proj [128,64]  | 7 b_proj [64]      Output: [B,N,64] f32
// ============================================================================
extern "C" void kernel_launch(void* const* d_in, const int* in_sizes, int n_in,
                              void* d_out, int out_size)
{
    const float* x     = (const float*)d_in[0];
    const float* adj   = (const float*)d_in[1];
    const float* mask  = (const float*)d_in[2];
    const float* Wemb  = (const float*)d_in[3];
    const float* Wl    = (const float*)d_in[4];
    const float* bl    = (const float*)d_in[5];
    const float* Wproj = (const float*)d_in[6];
    const float* bproj = (const float*)d_in[7];
    float* out = (float*)d_out;

    float *h_ptr = nullptr, *msgT_ptr = nullptr;
    cudaGetSymbolAddress((void**)&h_ptr, g_h);
    cudaGetSymbolAddress((void**)&msgT_ptr, g_msgT);

    cudaFuncSetAttribute(adj_mma_relu,
                         cudaFuncAttributeMaxDynamicSharedMemorySize, SM_TOTAL);

    const int nrows = BB * NN;            // 32768
    dim3 sidegrid(nrows / 128);           // 256 blocks
    dim3 bigg(NN / 128, BB);              // (8, 32)

    // 1) embed: h = x @ W_embed
    tile_gemm<IN_DIM, HID, false, false, false><<<sidegrid, 256>>>(
        x, Wemb, nullptr, nullptr, h_ptr);

    // 2) GCN layers: msgT = (h @ Wl + bl)^T ; h = relu(adj @ msgT^T)
    for (int l = 0; l < NUM_LAYERS; l++) {
        tile_gemm<HID, HID, true, false, true><<<sidegrid, 256>>>(
            h_ptr, Wl + (size_t)l * HID * HID, bl + (size_t)l * HID, nullptr, msgT_ptr);
        adj_mma_relu<<<bigg, 256, SM_TOTAL>>>(adj, msgT_ptr, h_ptr);
    }

    // 3) projection + mask
    tile_gemm<HID, OUTD, true, true, false><<<sidegrid, 256>>>(
        h_ptr, Wproj, bproj, mask, out);
}

// round 8
// speedup vs baseline: 4.3881x; 1.5181x over previous
#include <cuda_runtime.h>
#include <cuda_fp16.h>
#include <cstdint>

// Problem constants
#define BB 32
#define NN 1024
#define IN_DIM 64
#define HID 128
#define OUTD 64        // 2*LAT
#define NUM_LAYERS 3

// fp16 range management (all powers of two => exact):
//   hT buffers store h * SH  (SH = 1/16)
//   Tbuf stores T_true * SH * ST2 = T_true/1024  (ST2 = 1/64)
//   epilogue: h' = relu(acc2 * 1024 + rowsum*bl)
#define SH_F    0.0625f      // 2^-4
#define ST2_F   0.015625f    // 2^-6
#define UNSC_F  1024.0f      // 1/(SH*ST2)

// Scratch (device globals; no allocations allowed)
__device__ __half g_adjh[(size_t)BB * NN * NN];       // 67 MB fp16 adjacency
__device__ __half g_hT[2][(size_t)BB * HID * NN];     // ping-pong transposed activations (scaled by SH)
__device__ float  g_h[(size_t)BB * NN * HID];         // layer-2 normal-layout output (unscaled)
__device__ float  g_rowsum[BB * NN];                  // per-node adjacency row sums
__device__ __half g_WlTh[NUM_LAYERS * HID * HID];     // Wl transposed, fp16

// ============================================================================
// Helpers
// ============================================================================
__device__ __forceinline__ uint32_t smem_u32(const void* p) {
    uint32_t a;
    asm("{ .reg .u64 t; cvta.to.shared.u64 t, %1; cvt.u32.u64 %0, t; }"
        : "=r"(a) : "l"(p));
    return a;
}

__device__ __forceinline__ uint32_t pack_h2(float a, float b) {
    __half2 h = __floats2half2_rn(a, b);
    return *reinterpret_cast<uint32_t*>(&h);
}

__device__ __forceinline__ void mma_f16(float c[4],
                                        uint32_t a0, uint32_t a1, uint32_t a2, uint32_t a3,
                                        uint32_t b0, uint32_t b1) {
    asm volatile(
        "mma.sync.aligned.m16n8k16.row.col.f32.f16.f16.f32 "
        "{%0,%1,%2,%3}, {%4,%5,%6,%7}, {%8,%9}, {%0,%1,%2,%3};"
        : "+f"(c[0]), "+f"(c[1]), "+f"(c[2]), "+f"(c[3])
        : "r"(a0), "r"(a1), "r"(a2), "r"(a3), "r"(b0), "r"(b1));
}

#define CP_ASYNC16(dst, src) \
    asm volatile("cp.async.cg.shared.global [%0], [%1], 16;" :: "r"(dst), "l"(src))
#define CP_COMMIT() asm volatile("cp.async.commit_group;" ::: "memory")
#define CP_WAIT2()  asm volatile("cp.async.wait_group 2;" ::: "memory")
#define CP_WAIT0()  asm volatile("cp.async.wait_group 0;" ::: "memory")

// fp16 tile: 128 rows x 64 halves (128B rows). 16B word q at row r stored at
// word q ^ (r&7). Conflict-free for the m16n8k16 fragment access pattern.
// Half-pair p (2 halves, 4B) of row r lives at word p>>2, inner (p&3)*4.
__device__ __forceinline__ uint32_t lds_h2(const char* tile, int r, int w, int tg) {
    return *reinterpret_cast<const uint32_t*>(
        tile + r * 128 + (((w ^ (r & 7)) & 7) << 4) + tg * 4);
}

// Load one 16KB fp16 tile (128 rows x 64 halves) via cp.async, swizzled.
__device__ __forceinline__ void load_tile16(
    uint32_t dst, const __half* __restrict__ src, int rowstride_h, int tid)
{
#pragma unroll
    for (int i = 0; i < 4; i++) {
        int idx = tid + i * 256;             // 0..1023
        int row = idx >> 3;                  // 0..127
        int q   = idx & 7;                   // 16B word
        CP_ASYNC16(dst + row * 128 + ((q ^ (row & 7)) << 4),
                   src + (size_t)row * rowstride_h + q * 8);
    }
}

// ============================================================================
// Prep kernels
// ============================================================================
// WlT fp16: T[l][n2][n] = Wl[l][n][n2]
__global__ void prep_wlt(const float* __restrict__ Wl, __half* __restrict__ wlt) {
    int l = blockIdx.x;
    const float* W = Wl + (size_t)l * HID * HID;
    __half* T = wlt + (size_t)l * HID * HID;
    for (int i = threadIdx.x; i < HID * HID; i += blockDim.x) {
        int n2 = i >> 7, n = i & 127;
        T[i] = __float2half(W[n * HID + n2]);
    }
}

// adj fp32 -> fp16 copy + per-row sums. One warp per adjacency row.
__global__ __launch_bounds__(256) void conv_rowsum(
    const float* __restrict__ adj, __half* __restrict__ adjh, float* __restrict__ rs)
{
    int warp = (blockIdx.x * blockDim.x + threadIdx.x) >> 5;   // row id
    int lane = threadIdx.x & 31;
    const float* src = adj + (size_t)warp * NN;
    __half* dst = adjh + (size_t)warp * NN;
    float s = 0.f;
#pragma unroll
    for (int i = 0; i < 8; i++) {
        float4 v = *reinterpret_cast<const float4*>(src + i * 128 + lane * 4);
        s += v.x + v.y + v.z + v.w;
        union { __half2 h[2]; uint2 u; } pk;
        pk.h[0] = __floats2half2_rn(v.x, v.y);
        pk.h[1] = __floats2half2_rn(v.z, v.w);
        *reinterpret_cast<uint2*>(dst + i * 128 + lane * 4) = pk.u;
    }
#pragma unroll
    for (int off = 16; off; off >>= 1) s += __shfl_xor_sync(0xFFFFFFFFu, s, off);
    if (lane == 0) rs[warp] = s;
}

// ============================================================================
// Register-tiled side GEMM (SIMT fp32): C = (A[M,K] @ W[K,BN] + bias) (*mask),
// optional transposed output (fp16 hT, scaled by SH, for TRANS+HALFOUT).
// ============================================================================
template<int K, int BN, bool BIAS, bool MASK, bool TRANS, bool HALFOUT>
__global__ __launch_bounds__(256) void tile_gemm(
    const float* __restrict__ A, const float* __restrict__ W,
    const float* __restrict__ bias, const float* __restrict__ mask,
    void* __restrict__ Cv)
{
    constexpr int BM = 128, BK = 16;
    constexpr int VN = BN / 16;
    __shared__ float As[BK][BM + 4];
    __shared__ float Bs[BK][BN];

    const int tid  = threadIdx.x;
    const int tx   = tid & 15;
    const int ty   = tid >> 4;
    const int row0 = blockIdx.x * BM;
    const int col0 = tx * VN;

    float acc[8][VN];
#pragma unroll
    for (int i = 0; i < 8; i++)
#pragma unroll
        for (int j = 0; j < VN; j++) acc[i][j] = 0.f;

    for (int k0 = 0; k0 < K; k0 += BK) {
#pragma unroll
        for (int i = 0; i < 2; i++) {
            int f = tid + i * 256;
            int m = f >> 2, kq = f & 3;
            float4 v = *reinterpret_cast<const float4*>(
                &A[(size_t)(row0 + m) * K + k0 + kq * 4]);
            As[kq * 4 + 0][m] = v.x;
            As[kq * 4 + 1][m] = v.y;
            As[kq * 4 + 2][m] = v.z;
            As[kq * 4 + 3][m] = v.w;
        }
#pragma unroll
        for (int i = 0; i < (BK * BN) / (4 * 256); i++) {
            int f  = tid + i * 256;
            int kk = f / (BN / 4);
            int nq = f % (BN / 4);
            *reinterpret_cast<float4*>(&Bs[kk][nq * 4]) =
                *reinterpret_cast<const float4*>(&W[(size_t)(k0 + kk) * BN + nq * 4]);
        }
        __syncthreads();
#pragma unroll
        for (int k = 0; k < BK; k++) {
            float ra[8], rb[VN];
#pragma unroll
            for (int i = 0; i < 8; i++)  ra[i] = As[k][ty * 8 + i];
#pragma unroll
            for (int j = 0; j < VN; j++) rb[j] = Bs[k][col0 + j];
#pragma unroll
            for (int i = 0; i < 8; i++)
#pragma unroll
                for (int j = 0; j < VN; j++)
                    acc[i][j] += ra[i] * rb[j];
        }
        __syncthreads();
    }

    float bv[VN];
#pragma unroll
    for (int j = 0; j < VN; j++) bv[j] = BIAS ? bias[col0 + j] : 0.f;

    if (TRANS) {
        const int bb    = row0 >> 10;
        const int node0 = (row0 & (NN - 1)) + ty * 8;
#pragma unroll
        for (int j = 0; j < VN; j++) {
            if (HALFOUT) {
                __half* dst = (__half*)Cv + ((size_t)(bb * HID + col0 + j)) * NN + node0;
                union { __half2 h[4]; uint4 u; } pk;
#pragma unroll
                for (int i = 0; i < 4; i++)
                    pk.h[i] = __floats2half2_rn((acc[2 * i][j] + bv[j]) * SH_F,
                                                (acc[2 * i + 1][j] + bv[j]) * SH_F);
                *reinterpret_cast<uint4*>(dst) = pk.u;
            } else {
                float* dst = (float*)Cv + ((size_t)(bb * HID + col0 + j)) * NN + node0;
#pragma unroll
                for (int i = 0; i < 8; i += 4) {
                    float4 v;
                    v.x = acc[i + 0][j] + bv[j];
                    v.y = acc[i + 1][j] + bv[j];
                    v.z = acc[i + 2][j] + bv[j];
                    v.w = acc[i + 3][j] + bv[j];
                    *reinterpret_cast<float4*>(&dst[i]) = v;
                }
            }
        }
    } else {
        float* C = (float*)Cv;
#pragma unroll
        for (int i = 0; i < 8; i++) {
            int row = row0 + ty * 8 + i;
            float m = MASK ? mask[row] : 1.f;
#pragma unroll
            for (int j = 0; j < VN; j += 4) {
                float4 v;
                v.x = (acc[i][j + 0] + bv[j + 0]) * m;
                v.y = (acc[i][j + 1] + bv[j + 1]) * m;
                v.z = (acc[i][j + 2] + bv[j + 2]) * m;
                v.w = (acc[i][j + 3] + bv[j + 3]) * m;
                *reinterpret_cast<float4*>(&C[(size_t)row * BN + col0 + j]) = v;
            }
        }
    }
}

// ============================================================================
// Fused GCN layer (fp16 tensor cores):
//   acc = adjh[b] @ (h_in*SH)^T    (mainloop, m16n8k16, K=1024, BK=64 chunks)
//   Tbuf = acc * ST2 = T_true/1024 (fp16, overflow-safe)
//   h' = relu(1024 * (Tbuf @ Wl) + rowsum ⊗ bl)
//   LAST=false: store (h'*SH)^T fp16 ; LAST=true: store h' fp32 normal layout
// 8 warps, warp tile 64x32 (2x4 grid). 3-stage cp.async ring of 16KB tiles.
// ============================================================================
#define ST 3
#define BKH 64                     // K per chunk (64 halves = 128B row)
#define NITH (NN / BKH)            // 16
#define TILE16 16384
#define HBUF_OFF (4 * TILE16)      // h'buf overlaps slots 4,5 (epilogue only)
#define HBUF_STRIDE 136            // halves per feat row (272B, 16B-aligned)
#define SMTOT (HBUF_OFF + 128 * HBUF_STRIDE * 2)   // 100352 B

template<bool LAST>
__global__ __launch_bounds__(256, 2) void adj_layer(
    const __half* __restrict__ adjh, const __half* __restrict__ hTin,
    const __half* __restrict__ wlt,  const float* __restrict__ bl,
    const float* __restrict__ rowsum,
    __half* __restrict__ hTout, float* __restrict__ hnorm)
{
    extern __shared__ char smem[];
    const uint32_t sb = smem_u32(smem);
    const int tid = threadIdx.x;
    const int wid = tid >> 5;
    const int lid = tid & 31;
    const int g   = lid >> 2;
    const int tg  = lid & 3;

    const int m_warp = (wid & 1) * 64;
    const int n_warp = (wid >> 1) * 32;

    const int b    = blockIdx.y;
    const int row0 = blockIdx.x * 128;

    const __half* Ab = adjh + (size_t)b * NN * NN + (size_t)row0 * NN;
    const __half* Bb = hTin + (size_t)b * HID * NN;

    float acc[4][4][4];
#pragma unroll
    for (int mt = 0; mt < 4; mt++)
#pragma unroll
        for (int nt = 0; nt < 4; nt++)
#pragma unroll
            for (int r = 0; r < 4; r++) acc[mt][nt][r] = 0.f;

    // ---- mainloop: acc = adj @ (h*SH) ----
#pragma unroll
    for (int p = 0; p < ST; p++) {
        load_tile16(sb + p * TILE16, Ab + p * BKH, NN, tid);
        load_tile16(sb + (ST + p) * TILE16, Bb + p * BKH, NN, tid);
        CP_COMMIT();
    }

    for (int it = 0; it < NITH; it++) {
        const int s = it % ST;
        const char* As = smem + s * TILE16;
        const char* Bs = smem + (ST + s) * TILE16;

        CP_WAIT2();
        __syncthreads();

#pragma unroll
        for (int kk = 0; kk < 4; kk++) {          // 4 x K=16 steps per chunk
            uint32_t bf[4][2];
#pragma unroll
            for (int nt = 0; nt < 4; nt++) {
                int nr = n_warp + nt * 8 + g;
                bf[nt][0] = lds_h2(Bs, nr, 2 * kk,     tg);
                bf[nt][1] = lds_h2(Bs, nr, 2 * kk + 1, tg);
            }
#pragma unroll
            for (int mt = 0; mt < 4; mt++) {
                int mr = m_warp + mt * 16 + g;
                uint32_t a0 = lds_h2(As, mr,     2 * kk,     tg);
                uint32_t a1 = lds_h2(As, mr + 8, 2 * kk,     tg);
                uint32_t a2 = lds_h2(As, mr,     2 * kk + 1, tg);
                uint32_t a3 = lds_h2(As, mr + 8, 2 * kk + 1, tg);
#pragma unroll
                for (int nt = 0; nt < 4; nt++)
                    mma_f16(acc[mt][nt], a0, a1, a2, a3, bf[nt][0], bf[nt][1]);
            }
        }
        __syncthreads();

        if (it + ST < NITH) {
            load_tile16(sb + s * TILE16, Ab + (it + ST) * BKH, NN, tid);
            load_tile16(sb + (ST + s) * TILE16, Bb + (it + ST) * BKH, NN, tid);
        }
        CP_COMMIT();
    }

    // ---- epilogue: h' = relu(1024*(Tbuf @ Wl) + rowsum*bl) ----
    // Prefetch WlT chunks into slots 2,3 (rows n2=128, 64 k-halves each)
    load_tile16(sb + 2 * TILE16, wlt,      HID, tid);
    CP_COMMIT();
    load_tile16(sb + 3 * TILE16, wlt + 64, HID, tid);
    CP_COMMIT();

    // Write Tbuf = acc * ST2 (fp32 -> fp16) into slots 0 (cols 0-63) / 1 (64-127)
    {
        char* tb = smem + (n_warp >> 6) * TILE16;
        const int lpb = (n_warp & 63) >> 1;
#pragma unroll
        for (int mt = 0; mt < 4; mt++) {
            int mr = m_warp + mt * 16 + g;
#pragma unroll
            for (int nt = 0; nt < 4; nt++) {
                int lp = lpb + nt * 4 + tg;
                int w = lp >> 2, inner = (lp & 3) * 4;
                *reinterpret_cast<uint32_t*>(
                    tb + mr * 128 + (((w ^ (mr & 7))) << 4) + inner) =
                    pack_h2(acc[mt][nt][0] * ST2_F, acc[mt][nt][1] * ST2_F);
                *reinterpret_cast<uint32_t*>(
                    tb + (mr + 8) * 128 + (((w ^ ((mr + 8) & 7))) << 4) + inner) =
                    pack_h2(acc[mt][nt][2] * ST2_F, acc[mt][nt][3] * ST2_F);
            }
        }
    }
    CP_WAIT0();
    __syncthreads();

    float acc2[4][4][4];
#pragma unroll
    for (int mt = 0; mt < 4; mt++)
#pragma unroll
        for (int nt = 0; nt < 4; nt++)
#pragma unroll
            for (int r = 0; r < 4; r++) acc2[mt][nt][r] = 0.f;

#pragma unroll
    for (int ch = 0; ch < 2; ch++) {
        const char* Ts = smem + ch * TILE16;
        const char* Ws = smem + (2 + ch) * TILE16;
#pragma unroll
        for (int kk = 0; kk < 4; kk++) {
            uint32_t bf[4][2];
#pragma unroll
            for (int nt = 0; nt < 4; nt++) {
                int nr = n_warp + nt * 8 + g;      // n2 rows of WlT
                bf[nt][0] = lds_h2(Ws, nr, 2 * kk,     tg);
                bf[nt][1] = lds_h2(Ws, nr, 2 * kk + 1, tg);
            }
#pragma unroll
            for (int mt = 0; mt < 4; mt++) {
                int mr = m_warp + mt * 16 + g;
                uint32_t a0 = lds_h2(Ts, mr,     2 * kk,     tg);
                uint32_t a1 = lds_h2(Ts, mr + 8, 2 * kk,     tg);
                uint32_t a2 = lds_h2(Ts, mr,     2 * kk + 1, tg);
                uint32_t a3 = lds_h2(Ts, mr + 8, 2 * kk + 1, tg);
#pragma unroll
                for (int nt = 0; nt < 4; nt++)
                    mma_f16(acc2[mt][nt], a0, a1, a2, a3, bf[nt][0], bf[nt][1]);
            }
        }
    }

    // bias (rowsum * bl) + relu + store
    const float* rsb = rowsum + b * NN + row0;
    float rlo[4], rhi[4];
#pragma unroll
    for (int mt = 0; mt < 4; mt++) {
        rlo[mt] = rsb[m_warp + mt * 16 + g];
        rhi[mt] = rsb[m_warp + mt * 16 + g + 8];
    }
    float b0v[4], b1v[4];
#pragma unroll
    for (int nt = 0; nt < 4; nt++) {
        int col = n_warp + nt * 8 + 2 * tg;
        b0v[nt] = bl[col];
        b1v[nt] = bl[col + 1];
    }

    __half* hb = reinterpret_cast<__half*>(smem + HBUF_OFF);

#pragma unroll
    for (int mt = 0; mt < 4; mt++) {
        int mr = m_warp + mt * 16 + g;
#pragma unroll
        for (int nt = 0; nt < 4; nt++) {
            int col = n_warp + nt * 8 + 2 * tg;
            float v00 = fmaxf(fmaf(acc2[mt][nt][0], UNSC_F, rlo[mt] * b0v[nt]), 0.f);
            float v01 = fmaxf(fmaf(acc2[mt][nt][1], UNSC_F, rlo[mt] * b1v[nt]), 0.f);
            float v10 = fmaxf(fmaf(acc2[mt][nt][2], UNSC_F, rhi[mt] * b0v[nt]), 0.f);
            float v11 = fmaxf(fmaf(acc2[mt][nt][3], UNSC_F, rhi[mt] * b1v[nt]), 0.f);
            if (LAST) {
                float2 p0 = make_float2(v00, v01);
                float2 p1 = make_float2(v10, v11);
                *reinterpret_cast<float2*>(
                    &hnorm[(size_t)(b * NN + row0 + mr) * HID + col]) = p0;
                *reinterpret_cast<float2*>(
                    &hnorm[(size_t)(b * NN + row0 + mr + 8) * HID + col]) = p1;
            } else {
                hb[(col)     * HBUF_STRIDE + mr]     = __float2half(v00 * SH_F);
                hb[(col + 1) * HBUF_STRIDE + mr]     = __float2half(v01 * SH_F);
                hb[(col)     * HBUF_STRIDE + mr + 8] = __float2half(v10 * SH_F);
                hb[(col + 1) * HBUF_STRIDE + mr + 8] = __float2half(v11 * SH_F);
            }
        }
    }

    if (!LAST) {
        __syncthreads();
        // coalesced h'T store: feat row c -> hTout[b][c][row0 .. row0+127]
#pragma unroll
        for (int p = 0; p < 8; p++) {
            int idx = tid + p * 256;
            int c = idx >> 4, u = idx & 15;
            uint4 v = *reinterpret_cast<const uint4*>(hb + c * HBUF_STRIDE + u * 8);
            *reinterpret_cast<uint4*>(
                hTout + ((size_t)(b * HID + c)) * NN + row0 + u * 8) = v;
        }
    }
}

// ============================================================================
// Launch
// Inputs: 0 node_features [B,N,64] | 1 adjacency [B,N,N] | 2 node_mask [B,N,1]
//         3 W_embed [64,128] | 4 Wl [3,128,128] | 5 bl [3,128]
//         6 W_proj [128,64]  | 7 b_proj [64]      Output: [B,N,64] f32
// ============================================================================
extern "C" void kernel_launch(void* const* d_in, const int* in_sizes, int n_in,
                              void* d_out, int out_size)
{
    const float* x     = (const float*)d_in[0];
    const float* adj   = (const float*)d_in[1];
    const float* mask  = (const float*)d_in[2];
    const float* Wemb  = (const float*)d_in[3];
    const float* Wl    = (const float*)d_in[4];
    const float* bl    = (const float*)d_in[5];
    const float* Wproj = (const float*)d_in[6];
    const float* bproj = (const float*)d_in[7];
    float* out = (float*)d_out;

    __half *adjh = nullptr, *hT = nullptr, *wlt = nullptr;
    float *h_ptr = nullptr, *rs = nullptr;
    cudaGetSymbolAddress((void**)&adjh, g_adjh);
    cudaGetSymbolAddress((void**)&hT,   g_hT);
    cudaGetSymbolAddress((void**)&wlt,  g_WlTh);
    cudaGetSymbolAddress((void**)&h_ptr, g_h);
    cudaGetSymbolAddress((void**)&rs,    g_rowsum);
    __half* hT0 = hT;
    __half* hT1 = hT + (size_t)BB * HID * NN;

    cudaFuncSetAttribute(adj_layer<false>,
                         cudaFuncAttributeMaxDynamicSharedMemorySize, SMTOT);
    cudaFuncSetAttribute(adj_layer<true>,
                         cudaFuncAttributeMaxDynamicSharedMemorySize, SMTOT);

    // prep: WlT fp16; adj fp16 + rowsum; embed hT0 = (x @ Wemb)^T * SH, fp16
    prep_wlt<<<NUM_LAYERS, 256>>>(Wl, wlt);
    tile_gemm<IN_DIM, HID, false, false, true, true><<<BB * NN / 128, 256>>>(
        x, Wemb, nullptr, nullptr, hT0);
    conv_rowsum<<<BB * NN / 8, 256>>>(adj, adjh, rs);

    dim3 bigg(NN / 128, BB);   // (8, 32)
    adj_layer<false><<<bigg, 256, SMTOT>>>(adjh, hT0, wlt,                 bl,
                                           rs, hT1, nullptr);
    adj_layer<false><<<bigg, 256, SMTOT>>>(adjh, hT1, wlt + HID * HID,     bl + HID,
                                           rs, hT0, nullptr);
    adj_layer<true ><<<bigg, 256, SMTOT>>>(adjh, hT0, wlt + 2 * HID * HID, bl + 2 * HID,
                                           rs, nullptr, h_ptr);

    // projection + mask (SIMT fp32)
    tile_gemm<HID, OUTD, true, true, false, false><<<BB * NN / 128, 256>>>(
        h_ptr, Wproj, bproj, mask, out);
}

// round 10
// speedup vs baseline: 5.4824x; 1.2494x over previous
#include <cuda_runtime.h>
#include <cuda_fp16.h>
#include <cstdint>

// Problem constants
#define BB 32
#define NN 1024
#define IN_DIM 64
#define HID 128
#define OUTD 64        // 2*LAT
#define NUM_LAYERS 3

// fp16 range management (all powers of two => exact):
//   hT buffers store h * SH  (SH = 1/16)
//   Tbuf stores T_true * SH * ST2 = T_true/1024  (ST2 = 1/64)
//   epilogue: h' = relu(acc2 * 1024 + rowsum*bl)
#define SH_F    0.0625f      // 2^-4
#define ST2_F   0.015625f    // 2^-6
#define UNSC_F  1024.0f      // 1/(SH*ST2)

// Scratch (device globals; no allocations allowed)
__device__ __half g_adjh[(size_t)BB * NN * NN];       // 67 MB fp16 adjacency
__device__ __half g_hT[2][(size_t)BB * HID * NN];     // ping-pong transposed activations (scaled by SH)
__device__ float  g_h[(size_t)BB * NN * HID];         // layer-2 normal-layout output (unscaled)
__device__ float  g_rowsum[BB * NN];                  // per-node adjacency row sums
__device__ __half g_WlTh[NUM_LAYERS * HID * HID];     // Wl transposed, fp16

// ============================================================================
// Helpers
// ============================================================================
__device__ __forceinline__ uint32_t smem_u32(const void* p) {
    uint32_t a;
    asm("{ .reg .u64 t; cvta.to.shared.u64 t, %1; cvt.u32.u64 %0, t; }"
        : "=r"(a) : "l"(p));
    return a;
}

__device__ __forceinline__ uint32_t pack_h2(float a, float b) {
    __half2 h = __floats2half2_rn(a, b);
    return *reinterpret_cast<uint32_t*>(&h);
}

__device__ __forceinline__ void mma_f16(float c[4],
                                        uint32_t a0, uint32_t a1, uint32_t a2, uint32_t a3,
                                        uint32_t b0, uint32_t b1) {
    asm volatile(
        "mma.sync.aligned.m16n8k16.row.col.f32.f16.f16.f32 "
        "{%0,%1,%2,%3}, {%4,%5,%6,%7}, {%8,%9}, {%0,%1,%2,%3};"
        : "+f"(c[0]), "+f"(c[1]), "+f"(c[2]), "+f"(c[3])
        : "r"(a0), "r"(a1), "r"(a2), "r"(a3), "r"(b0), "r"(b1));
}

#define LDMX4(r0, r1, r2, r3, addr) \
    asm volatile("ldmatrix.sync.aligned.m8n8.x4.shared.b16 {%0,%1,%2,%3}, [%4];" \
                 : "=r"(r0), "=r"(r1), "=r"(r2), "=r"(r3) : "r"(addr))

#define CP_ASYNC16(dst, src) \
    asm volatile("cp.async.cg.shared.global [%0], [%1], 16;" :: "r"(dst), "l"(src))
#define CP_COMMIT() asm volatile("cp.async.commit_group;" ::: "memory")
#define CP_WAIT1()  asm volatile("cp.async.wait_group 1;" ::: "memory")
#define CP_WAIT0()  asm volatile("cp.async.wait_group 0;" ::: "memory")

// fp16 tile: 128 rows x 64 halves (128B rows). 16B word q of row r stored at
// word q ^ (r&7). Conflict-free for both cp.async fill and ldmatrix reads.
__device__ __forceinline__ uint32_t lds_h2(const char* tile, int r, int w, int tg) {
    return *reinterpret_cast<const uint32_t*>(
        tile + r * 128 + (((w ^ (r & 7)) & 7) << 4) + tg * 4);
}

// Load one 16KB fp16 tile (128 rows x 64 halves) via cp.async, swizzled.
__device__ __forceinline__ void load_tile16(
    uint32_t dst, const __half* __restrict__ src, int rowstride_h, int tid)
{
#pragma unroll
    for (int i = 0; i < 4; i++) {
        int idx = tid + i * 256;             // 0..1023
        int row = idx >> 3;                  // 0..127
        int q   = idx & 7;                   // 16B word
        CP_ASYNC16(dst + row * 128 + ((q ^ (row & 7)) << 4),
                   src + (size_t)row * rowstride_h + q * 8);
    }
}

// ============================================================================
// Prep kernels
// ============================================================================
__global__ void prep_wlt(const float* __restrict__ Wl, __half* __restrict__ wlt) {
    int l = blockIdx.x;
    const float* W = Wl + (size_t)l * HID * HID;
    __half* T = wlt + (size_t)l * HID * HID;
    for (int i = threadIdx.x; i < HID * HID; i += blockDim.x) {
        int n2 = i >> 7, n = i & 127;
        T[i] = __float2half(W[n * HID + n2]);
    }
}

// adj fp32 -> fp16 copy + per-row sums. One warp per adjacency row.
__global__ __launch_bounds__(256) void conv_rowsum(
    const float* __restrict__ adj, __half* __restrict__ adjh, float* __restrict__ rs)
{
    int warp = (blockIdx.x * blockDim.x + threadIdx.x) >> 5;   // row id
    int lane = threadIdx.x & 31;
    const float* src = adj + (size_t)warp * NN;
    __half* dst = adjh + (size_t)warp * NN;
    float s = 0.f;
#pragma unroll
    for (int i = 0; i < 8; i++) {
        float4 v = *reinterpret_cast<const float4*>(src + i * 128 + lane * 4);
        s += v.x + v.y + v.z + v.w;
        union { __half2 h[2]; uint2 u; } pk;
        pk.h[0] = __floats2half2_rn(v.x, v.y);
        pk.h[1] = __floats2half2_rn(v.z, v.w);
        *reinterpret_cast<uint2*>(dst + i * 128 + lane * 4) = pk.u;
    }
#pragma unroll
    for (int off = 16; off; off >>= 1) s += __shfl_xor_sync(0xFFFFFFFFu, s, off);
    if (lane == 0) rs[warp] = s;
}

// ============================================================================
// Register-tiled side GEMM (SIMT fp32): C = (A[M,K] @ W[K,BN] + bias) (*mask),
// optional transposed output (fp16 hT, scaled by SH, for TRANS+HALFOUT).
// ============================================================================
template<int K, int BN, bool BIAS, bool MASK, bool TRANS, bool HALFOUT>
__global__ __launch_bounds__(256) void tile_gemm(
    const float* __restrict__ A, const float* __restrict__ W,
    const float* __restrict__ bias, const float* __restrict__ mask,
    void* __restrict__ Cv)
{
    constexpr int BM = 128, BK = 16;
    constexpr int VN = BN / 16;
    __shared__ float As[BK][BM + 4];
    __shared__ float Bs[BK][BN];

    const int tid  = threadIdx.x;
    const int tx   = tid & 15;
    const int ty   = tid >> 4;
    const int row0 = blockIdx.x * BM;
    const int col0 = tx * VN;

    float acc[8][VN];
#pragma unroll
    for (int i = 0; i < 8; i++)
#pragma unroll
        for (int j = 0; j < VN; j++) acc[i][j] = 0.f;

    for (int k0 = 0; k0 < K; k0 += BK) {
#pragma unroll
        for (int i = 0; i < 2; i++) {
            int f = tid + i * 256;
            int m = f >> 2, kq = f & 3;
            float4 v = *reinterpret_cast<const float4*>(
                &A[(size_t)(row0 + m) * K + k0 + kq * 4]);
            As[kq * 4 + 0][m] = v.x;
            As[kq * 4 + 1][m] = v.y;
            As[kq * 4 + 2][m] = v.z;
            As[kq * 4 + 3][m] = v.w;
        }
#pragma unroll
        for (int i = 0; i < (BK * BN) / (4 * 256); i++) {
            int f  = tid + i * 256;
            int kk = f / (BN / 4);
            int nq = f % (BN / 4);
            *reinterpret_cast<float4*>(&Bs[kk][nq * 4]) =
                *reinterpret_cast<const float4*>(&W[(size_t)(k0 + kk) * BN + nq * 4]);
        }
        __syncthreads();
#pragma unroll
        for (int k = 0; k < BK; k++) {
            float ra[8], rb[VN];
#pragma unroll
            for (int i = 0; i < 8; i++)  ra[i] = As[k][ty * 8 + i];
#pragma unroll
            for (int j = 0; j < VN; j++) rb[j] = Bs[k][col0 + j];
#pragma unroll
            for (int i = 0; i < 8; i++)
#pragma unroll
                for (int j = 0; j < VN; j++)
                    acc[i][j] += ra[i] * rb[j];
        }
        __syncthreads();
    }

    float bv[VN];
#pragma unroll
    for (int j = 0; j < VN; j++) bv[j] = BIAS ? bias[col0 + j] : 0.f;

    if (TRANS) {
        const int bb    = row0 >> 10;
        const int node0 = (row0 & (NN - 1)) + ty * 8;
#pragma unroll
        for (int j = 0; j < VN; j++) {
            if (HALFOUT) {
                __half* dst = (__half*)Cv + ((size_t)(bb * HID + col0 + j)) * NN + node0;
                union { __half2 h[4]; uint4 u; } pk;
#pragma unroll
                for (int i = 0; i < 4; i++)
                    pk.h[i] = __floats2half2_rn((acc[2 * i][j] + bv[j]) * SH_F,
                                                (acc[2 * i + 1][j] + bv[j]) * SH_F);
                *reinterpret_cast<uint4*>(dst) = pk.u;
            } else {
                float* dst = (float*)Cv + ((size_t)(bb * HID + col0 + j)) * NN + node0;
#pragma unroll
                for (int i = 0; i < 8; i += 4) {
                    float4 v;
                    v.x = acc[i + 0][j] + bv[j];
                    v.y = acc[i + 1][j] + bv[j];
                    v.z = acc[i + 2][j] + bv[j];
                    v.w = acc[i + 3][j] + bv[j];
                    *reinterpret_cast<float4*>(&dst[i]) = v;
                }
            }
        }
    } else {
        float* C = (float*)Cv;
#pragma unroll
        for (int i = 0; i < 8; i++) {
            int row = row0 + ty * 8 + i;
            float m = MASK ? mask[row] : 1.f;
#pragma unroll
            for (int j = 0; j < VN; j += 4) {
                float4 v;
                v.x = (acc[i][j + 0] + bv[j + 0]) * m;
                v.y = (acc[i][j + 1] + bv[j + 1]) * m;
                v.z = (acc[i][j + 2] + bv[j + 2]) * m;
                v.w = (acc[i][j + 3] + bv[j + 3]) * m;
                *reinterpret_cast<float4*>(&C[(size_t)row * BN + col0 + j]) = v;
            }
        }
    }
}

// ============================================================================
// Fused GCN layer (fp16 tensor cores, ldmatrix fragment loads):
//   acc = adjh[b] @ (h_in*SH)^T ; Tbuf = acc/64 ; h' = relu(1024*(Tbuf@Wl)+rs*bl)
// 8 warps, warp tile 64x32. 3-stage cp.async ring, single barrier per iter.
// ============================================================================
#define ST 3
#define BKH 64                     // K per chunk (64 halves = 128B row)
#define NITH (NN / BKH)            // 16
#define TILE16 16384
#define HBUF_OFF (4 * TILE16)      // h'buf overlaps slots 4,5 (epilogue only)
#define HBUF_STRIDE 136            // halves per feat row (272B, 16B-aligned)
#define SMTOT (HBUF_OFF + 128 * HBUF_STRIDE * 2)   // 100352 B

template<bool LAST>
__global__ __launch_bounds__(256, 2) void adj_layer(
    const __half* __restrict__ adjh, const __half* __restrict__ hTin,
    const __half* __restrict__ wlt,  const float* __restrict__ bl,
    const float* __restrict__ rowsum,
    __half* __restrict__ hTout, float* __restrict__ hnorm)
{
    extern __shared__ __align__(1024) char smem[];
    const uint32_t sb = smem_u32(smem);
    const int tid = threadIdx.x;
    const int wid = tid >> 5;
    const int lid = tid & 31;
    const int g   = lid >> 2;
    const int tg  = lid & 3;

    const int m_warp = (wid & 1) * 64;
    const int n_warp = (wid >> 1) * 32;

    const int b    = blockIdx.y;
    const int row0 = blockIdx.x * 128;

    const __half* Ab = adjh + (size_t)b * NN * NN + (size_t)row0 * NN;
    const __half* Bb = hTin + (size_t)b * HID * NN;

    // ---- ldmatrix lane-address precompute ----
    // A (x4 per mt): matrices [r0-7,k0-7],[r8-15,k0-7],[r0-7,k8-15],[r8-15,k8-15]
    //   lane l: row block = (l>>3)&1, w0 = (l>>4)&1, row-in-8 = l&7.
    // addr(tile) = r*128 + ((w ^ (r&7))<<4), w = 2kk + w0.
    // shifts distribute over XOR => addr = Q ^ (kk<<5), Q loop-invariant.
    const int xr  = lid & 7;
    const int rAo = ((lid >> 3) & 1) * 8;
    const int w0A = (lid >> 4) & 1;
    uint32_t Qa[4];
#pragma unroll
    for (int mt = 0; mt < 4; mt++) {
        int r = m_warp + mt * 16 + rAo + xr;
        Qa[mt] = (uint32_t)(r * 128 + ((w0A ^ xr) << 4));
    }
    // B (x4 per nt pair): matrices [nt,w0=0],[nt,w0=1],[nt+1,w0=0],[nt+1,w0=1]
    //   lane l: nt offset = (l>>4)&1, w0 = (l>>3)&1, row-in-8 = l&7.
    const int w0B = (lid >> 3) & 1;
    const int ntB = (lid >> 4) & 1;
    uint32_t Qb[2];
#pragma unroll
    for (int p = 0; p < 2; p++) {
        int rn = n_warp + (p * 2 + ntB) * 8 + xr;
        Qb[p] = (uint32_t)(rn * 128 + ((w0B ^ xr) << 4));
    }

    float acc[4][4][4];
#pragma unroll
    for (int mt = 0; mt < 4; mt++)
#pragma unroll
        for (int nt = 0; nt < 4; nt++)
#pragma unroll
            for (int r = 0; r < 4; r++) acc[mt][nt][r] = 0.f;

    // ---- mainloop: acc = adj @ (h*SH). Single barrier/iter, loads-first. ----
    // Preload chunks 0,1 (group index == chunk index via unconditional commit).
#pragma unroll
    for (int p = 0; p < 2; p++) {
        load_tile16(sb + p * TILE16, Ab + p * BKH, NN, tid);
        load_tile16(sb + (ST + p) * TILE16, Bb + p * BKH, NN, tid);
        CP_COMMIT();
    }

    for (int it = 0; it < NITH; it++) {
        const int s = it % ST;
        CP_WAIT1();                 // chunk 'it' arrived (groups 0..it done)
        __syncthreads();            // all warps done with MMA(it-1) -> slot (it+2)%ST free

        if (it + 2 < NITH) {
            const int sl = (it + 2) % ST;
            load_tile16(sb + sl * TILE16, Ab + (it + 2) * BKH, NN, tid);
            load_tile16(sb + (ST + sl) * TILE16, Bb + (it + 2) * BKH, NN, tid);
        }
        CP_COMMIT();                // unconditional: keeps group==chunk alignment

        const uint32_t sA = sb + s * TILE16;
        const uint32_t sB = sb + (ST + s) * TILE16;
#pragma unroll
        for (int kk = 0; kk < 4; kk++) {
            const uint32_t kx = (uint32_t)kk << 5;
            uint32_t bf[4][2];
            LDMX4(bf[0][0], bf[0][1], bf[1][0], bf[1][1], (sB + Qb[0]) ^ kx);
            LDMX4(bf[2][0], bf[2][1], bf[3][0], bf[3][1], (sB + Qb[1]) ^ kx);
#pragma unroll
            for (int mt = 0; mt < 4; mt++) {
                uint32_t a0, a1, a2, a3;
                LDMX4(a0, a1, a2, a3, (sA + Qa[mt]) ^ kx);
#pragma unroll
                for (int nt = 0; nt < 4; nt++)
                    mma_f16(acc[mt][nt], a0, a1, a2, a3, bf[nt][0], bf[nt][1]);
            }
        }
    }

    // ---- epilogue: h' = relu(1024*(Tbuf @ Wl) + rowsum*bl) ----
    // WlT ch0 -> slot 2 (A stage 2: idle since iter 14; iter-15 barrier proves it)
    load_tile16(sb + 2 * TILE16, wlt, HID, tid);
    CP_COMMIT();

    __syncthreads();                // all MMA(15) reads of slots 0/3 complete

    // WlT ch1 -> slot 3 (B stage 0: safe after the barrier above)
    load_tile16(sb + 3 * TILE16, wlt + 64, HID, tid);
    CP_COMMIT();

    // Tbuf = acc * ST2 (fp32 -> fp16) into slots 0 (cols 0-63) / 1 (64-127)
    {
        char* tb = smem + (n_warp >> 6) * TILE16;
        const int lpb = (n_warp & 63) >> 1;
#pragma unroll
        for (int mt = 0; mt < 4; mt++) {
            int mr = m_warp + mt * 16 + g;
#pragma unroll
            for (int nt = 0; nt < 4; nt++) {
                int lp = lpb + nt * 4 + tg;
                int w = lp >> 2, inner = (lp & 3) * 4;
                *reinterpret_cast<uint32_t*>(
                    tb + mr * 128 + (((w ^ (mr & 7))) << 4) + inner) =
                    pack_h2(acc[mt][nt][0] * ST2_F, acc[mt][nt][1] * ST2_F);
                *reinterpret_cast<uint32_t*>(
                    tb + (mr + 8) * 128 + (((w ^ ((mr + 8) & 7))) << 4) + inner) =
                    pack_h2(acc[mt][nt][2] * ST2_F, acc[mt][nt][3] * ST2_F);
            }
        }
    }
    CP_WAIT0();
    __syncthreads();

    float acc2[4][4][4];
#pragma unroll
    for (int mt = 0; mt < 4; mt++)
#pragma unroll
        for (int nt = 0; nt < 4; nt++)
#pragma unroll
            for (int r = 0; r < 4; r++) acc2[mt][nt][r] = 0.f;

#pragma unroll
    for (int ch = 0; ch < 2; ch++) {
        const uint32_t sT = sb + ch * TILE16;            // Tbuf
        const uint32_t sW = sb + (2 + ch) * TILE16;      // WlT
#pragma unroll
        for (int kk = 0; kk < 4; kk++) {
            const uint32_t kx = (uint32_t)kk << 5;
            uint32_t bf[4][2];
            LDMX4(bf[0][0], bf[0][1], bf[1][0], bf[1][1], (sW + Qb[0]) ^ kx);
            LDMX4(bf[2][0], bf[2][1], bf[3][0], bf[3][1], (sW + Qb[1]) ^ kx);
#pragma unroll
            for (int mt = 0; mt < 4; mt++) {
                uint32_t a0, a1, a2, a3;
                LDMX4(a0, a1, a2, a3, (sT + Qa[mt]) ^ kx);
#pragma unroll
                for (int nt = 0; nt < 4; nt++)
                    mma_f16(acc2[mt][nt], a0, a1, a2, a3, bf[nt][0], bf[nt][1]);
            }
        }
    }

    // bias (rowsum * bl) + relu + store
    const float* rsb = rowsum + b * NN + row0;
    float rlo[4], rhi[4];
#pragma unroll
    for (int mt = 0; mt < 4; mt++) {
        rlo[mt] = rsb[m_warp + mt * 16 + g];
        rhi[mt] = rsb[m_warp + mt * 16 + g + 8];
    }
    float b0v[4], b1v[4];
#pragma unroll
    for (int nt = 0; nt < 4; nt++) {
        int col = n_warp + nt * 8 + 2 * tg;
        b0v[nt] = bl[col];
        b1v[nt] = bl[col + 1];
    }

    __half* hb = reinterpret_cast<__half*>(smem + HBUF_OFF);

#pragma unroll
    for (int mt = 0; mt < 4; mt++) {
        int mr = m_warp + mt * 16 + g;
#pragma unroll
        for (int nt = 0; nt < 4; nt++) {
            int col = n_warp + nt * 8 + 2 * tg;
            float v00 = fmaxf(fmaf(acc2[mt][nt][0], UNSC_F, rlo[mt] * b0v[nt]), 0.f);
            float v01 = fmaxf(fmaf(acc2[mt][nt][1], UNSC_F, rlo[mt] * b1v[nt]), 0.f);
            float v10 = fmaxf(fmaf(acc2[mt][nt][2], UNSC_F, rhi[mt] * b0v[nt]), 0.f);
            float v11 = fmaxf(fmaf(acc2[mt][nt][3], UNSC_F, rhi[mt] * b1v[nt]), 0.f);
            if (LAST) {
                float2 p0 = make_float2(v00, v01);
                float2 p1 = make_float2(v10, v11);
                *reinterpret_cast<float2*>(
                    &hnorm[(size_t)(b * NN + row0 + mr) * HID + col]) = p0;
                *reinterpret_cast<float2*>(
                    &hnorm[(size_t)(b * NN + row0 + mr + 8) * HID + col]) = p1;
            } else {
                hb[(col)     * HBUF_STRIDE + mr]     = __float2half(v00 * SH_F);
                hb[(col + 1) * HBUF_STRIDE + mr]     = __float2half(v01 * SH_F);
                hb[(col)     * HBUF_STRIDE + mr + 8] = __float2half(v10 * SH_F);
                hb[(col + 1) * HBUF_STRIDE + mr + 8] = __float2half(v11 * SH_F);
            }
        }
    }

    if (!LAST) {
        __syncthreads();
        // coalesced h'T store: feat row c -> hTout[b][c][row0 .. row0+127]
#pragma unroll
        for (int p = 0; p < 8; p++) {
            int idx = tid + p * 256;
            int c = idx >> 4, u = idx & 15;
            uint4 v = *reinterpret_cast<const uint4*>(hb + c * HBUF_STRIDE + u * 8);
            *reinterpret_cast<uint4*>(
                hTout + ((size_t)(b * HID + c)) * NN + row0 + u * 8) = v;
        }
    }
}

// ============================================================================
// Launch
// Inputs: 0 node_features [B,N,64] | 1 adjacency [B,N,N] | 2 node_mask [B,N,1]
//         3 W_embed [64,128] | 4 Wl [3,128,128] | 5 bl [3,128]
//         6 W_proj [128,64]  | 7 b_proj [64]      Output: [B,N,64] f32
// ============================================================================
extern "C" void kernel_launch(void* const* d_in, const int* in_sizes, int n_in,
                              void* d_out, int out_size)
{
    const float* x     = (const float*)d_in[0];
    const float* adj   = (const float*)d_in[1];
    const float* mask  = (const float*)d_in[2];
    const float* Wemb  = (const float*)d_in[3];
    const float* Wl    = (const float*)d_in[4];
    const float* bl    = (const float*)d_in[5];
    const float* Wproj = (const float*)d_in[6];
    const float* bproj = (const float*)d_in[7];
    float* out = (float*)d_out;

    __half *adjh = nullptr, *hT = nullptr, *wlt = nullptr;
    float *h_ptr = nullptr, *rs = nullptr;
    cudaGetSymbolAddress((void**)&adjh, g_adjh);
    cudaGetSymbolAddress((void**)&hT,   g_hT);
    cudaGetSymbolAddress((void**)&wlt,  g_WlTh);
    cudaGetSymbolAddress((void**)&h_ptr, g_h);
    cudaGetSymbolAddress((void**)&rs,    g_rowsum);
    __half* hT0 = hT;
    __half* hT1 = hT + (size_t)BB * HID * NN;

    cudaFuncSetAttribute(adj_layer<false>,
                         cudaFuncAttributeMaxDynamicSharedMemorySize, SMTOT);
    cudaFuncSetAttribute(adj_layer<true>,
                         cudaFuncAttributeMaxDynamicSharedMemorySize, SMTOT);

    // prep: WlT fp16; adj fp16 + rowsum; embed hT0 = (x @ Wemb)^T * SH, fp16
    prep_wlt<<<NUM_LAYERS, 256>>>(Wl, wlt);
    tile_gemm<IN_DIM, HID, false, false, true, true><<<BB * NN / 128, 256>>>(
        x, Wemb, nullptr, nullptr, hT0);
    conv_rowsum<<<BB * NN / 8, 256>>>(adj, adjh, rs);

    dim3 bigg(NN / 128, BB);   // (8, 32)
    adj_layer<false><<<bigg, 256, SMTOT>>>(adjh, hT0, wlt,                 bl,
                                           rs, hT1, nullptr);
    adj_layer<false><<<bigg, 256, SMTOT>>>(adjh, hT1, wlt + HID * HID,     bl + HID,
                                           rs, hT0, nullptr);
    adj_layer<true ><<<bigg, 256, SMTOT>>>(adjh, hT0, wlt + 2 * HID * HID, bl + 2 * HID,
                                           rs, nullptr, h_ptr);

    // projection + mask (SIMT fp32)
    tile_gemm<HID, OUTD, true, true, false, false><<<BB * NN / 128, 256>>>(
        h_ptr, Wproj, bproj, mask, out);
}